// round 12
// baseline (speedup 1.0000x reference)
#include <cuda_runtime.h>

// B, N, D, L = 32, 1000, 256, 3
#define BB 32
#define NN 1000
#define DD 256
#define LL 3
#define CHUNKS 50
#define ROWS_PER_CHUNK 20         // 50 * 20 = 1000
#define TOTAL4 (BB * NN * DD / 4) // 2,048,000 float4s per output half

// Scratch (no device allocation allowed -> __device__ globals)
__device__ float g_partial[BB * CHUNKS * DD];
__device__ float g_v[BB * DD];

// ---------------------------------------------------------------------------
// K1: partial sums of node_feature over the node axis (pure read).
// grid (B, 50) = 1600 CTAs, block (64,4), 5 front-batched LDG.128.
// With .wt output stores (K3), nf should stay L2-resident across replays and
// this kernel should become a pure L2-hit read with no drain competition.
// ---------------------------------------------------------------------------
__global__ void k_partial_mean(const float* __restrict__ nf) {
    const int b = blockIdx.x;
    const int c = blockIdx.y;
    const int x = threadIdx.x;   // 0..63
    const int y = threadIdx.y;   // 0..3

    const float4* __restrict__ nf4 = reinterpret_cast<const float4*>(nf);
    const int base = (b * NN + c * ROWS_PER_CHUNK) * 64;

    const float4 a0 = nf4[base + (y +  0) * 64 + x];
    const float4 a1 = nf4[base + (y +  4) * 64 + x];
    const float4 a2 = nf4[base + (y +  8) * 64 + x];
    const float4 a3 = nf4[base + (y + 12) * 64 + x];
    const float4 a4 = nf4[base + (y + 16) * 64 + x];

    float4 s;
    s.x = (a0.x + a1.x) + (a2.x + a3.x) + a4.x;
    s.y = (a0.y + a1.y) + (a2.y + a3.y) + a4.y;
    s.z = (a0.z + a1.z) + (a2.z + a3.z) + a4.z;
    s.w = (a0.w + a1.w) + (a2.w + a3.w) + a4.w;

    __shared__ float4 sm[4][64];
    sm[y][x] = s;
    __syncthreads();
    if (y == 0) {
        float4 t = sm[0][x];
        const float4 t1 = sm[1][x], t2 = sm[2][x], t3 = sm[3][x];
        t.x += t1.x + t2.x + t3.x;
        t.y += t1.y + t2.y + t3.y;
        t.z += t1.z + t2.z + t3.z;
        t.w += t1.w + t2.w + t3.w;
        reinterpret_cast<float4*>(g_partial)[(b * CHUNKS + c) * 64 + x] = t;
    }
}

// ---------------------------------------------------------------------------
// K2: finish the mean, then 3 fused 256x256 GEMVs (+bias, ReLU between).
// One CTA per batch, 1024 threads: out-column o = t&255, K-group g = t>>8.
// (Champion shape — unchanged.)
// ---------------------------------------------------------------------------
__global__ void k_gcn_head(const float* __restrict__ Ws, const float* __restrict__ bs) {
    const int b = blockIdx.x;
    const int t = threadIdx.x;
    const int o = t & (DD - 1);
    const int g = t >> 8;       // 0..3

    __shared__ float sv[DD];
    __shared__ float part[4][DD];

    float s = 0.f;
    for (int c = g; c < CHUNKS; c += 4)
        s += g_partial[(b * CHUNKS + c) * DD + o];
    part[g][o] = s;
    __syncthreads();
    if (g == 0)
        sv[o] = (part[0][o] + part[1][o] + part[2][o] + part[3][o]) * (1.0f / (float)NN);
    __syncthreads();

#pragma unroll
    for (int l = 0; l < LL; l++) {
        const float* __restrict__ W = Ws + l * DD * DD;
        float acc = 0.f;
        const int k0 = g * 64;
#pragma unroll 8
        for (int k = k0; k < k0 + 64; k++)
            acc = fmaf(sv[k], W[k * DD + o], acc);   // coalesced, L2-resident
        part[g][o] = acc;
        __syncthreads();
        if (g == 0) {
            float r = part[0][o] + part[1][o] + part[2][o] + part[3][o] + bs[l * DD + o];
            sv[o] = (l < LL - 1) ? fmaxf(r, 0.f) : r;
        }
        __syncthreads();
    }
    if (g == 0) g_v[b * DD + o] = sv[o];
}

// ---------------------------------------------------------------------------
// K3: out[0:BND]     = node_feature + v[b,:]
//     out[BND:2BND]  = node_feature (copy)
// Champion shape, but stores use __stwt (write-through, NO L2 allocation):
// the 64MB output stream no longer pollutes L2 or defers drain into the
// next replay's K1.
// ---------------------------------------------------------------------------
__global__ void k_out(const float* __restrict__ nf, float* __restrict__ out) {
    const int stride = gridDim.x * blockDim.x;           // 512,000
    const int i0 = blockIdx.x * blockDim.x + threadIdx.x;

    const float4* __restrict__ nf4 = reinterpret_cast<const float4*>(nf);
    float4* o4 = reinterpret_cast<float4*>(out);

    const int ia = i0, ib = i0 + stride, ic = i0 + 2 * stride, id = i0 + 3 * stride;

    const float4 a0 = nf4[ia];
    const float4 a1 = nf4[ib];
    const float4 a2 = nf4[ic];
    const float4 a3 = nf4[id];

#define DO_ONE(idx, a)                                                        \
    {                                                                         \
        const int i = (idx) << 2;                                             \
        const int bb = i / (NN * DD);                                         \
        const int dd = i & (DD - 1);                                          \
        const float4 v = *reinterpret_cast<const float4*>(g_v + bb * DD + dd);\
        float4 r;                                                             \
        r.x = (a).x + v.x; r.y = (a).y + v.y;                                 \
        r.z = (a).z + v.z; r.w = (a).w + v.w;                                 \
        __stwt(o4 + (idx), r);                                                \
        __stwt(o4 + TOTAL4 + (idx), (a));                                     \
    }

    DO_ONE(ia, a0)
    DO_ONE(ib, a1)
    DO_ONE(ic, a2)
    DO_ONE(id, a3)
#undef DO_ONE
}

extern "C" void kernel_launch(void* const* d_in, const int* in_sizes, int n_in,
                              void* d_out, int out_size) {
    // Inputs in metadata order: x (unused), node_feature, Ws, bs
    const float* nf = (const float*)d_in[1];
    const float* Ws = (const float*)d_in[2];
    const float* bs = (const float*)d_in[3];
    float* out = (float*)d_out;

    dim3 g1(BB, CHUNKS);      // 1600 CTAs
    dim3 b1(64, 4);
    k_partial_mean<<<g1, b1>>>(nf);

    k_gcn_head<<<BB, 1024>>>(Ws, bs);

    // 2000 blocks * 256 threads * 4 float4/thread = 2,048,000 = TOTAL4 exactly
    k_out<<<2000, 256>>>(nf, out);
}

// round 13
// speedup vs baseline: 1.3701x; 1.3701x over previous
#include <cuda_runtime.h>

// B, N, D, L = 32, 1000, 256, 3
#define BB 32
#define NN 1000
#define DD 256
#define LL 3
#define CHUNKS 36
#define ROWS_PER_CHUNK 28          // 36 * 28 = 1008 >= 1000 (guarded)
#define TOTAL4 (BB * NN * DD / 4)  // 2,048,000 float4 per output half
#define B4 (NN * DD / 4)           // 64,000 float4 per batch

// Scratch (no device allocation allowed -> __device__ globals)
__device__ float g_partial[BB * CHUNKS * DD];
__device__ float g_v[BB * DD];

// ---------------------------------------------------------------------------
// K1: partial sums over the node axis — SINGLE WAVE.
// grid (32, 36) = 1152 CTAs (<= 148*8 co-resident), block (64,4).
// Thread (x,y): 7 front-batched LDG.128 covering rows y+4i, i=0..6 (28 rows),
// guarded against the 1000-row boundary (zero contributes nothing).
// ---------------------------------------------------------------------------
__global__ __launch_bounds__(256)
void k_partial_mean(const float* __restrict__ nf) {
    const int b = blockIdx.x;
    const int c = blockIdx.y;
    const int x = threadIdx.x;   // 0..63
    const int y = threadIdx.y;   // 0..3

    const float4* __restrict__ nf4 = reinterpret_cast<const float4*>(nf);
    const float4 z4 = make_float4(0.f, 0.f, 0.f, 0.f);
    const int row0 = c * ROWS_PER_CHUNK;
    const int base = (b * NN + row0) * 64;

    float4 a[7];
#pragma unroll
    for (int i = 0; i < 7; i++) {
        const int r = y + 4 * i;
        a[i] = (row0 + r < NN) ? nf4[base + r * 64 + x] : z4;
    }

    float4 s0 = z4, s1 = z4;
#pragma unroll
    for (int i = 0; i < 6; i += 2) {
        s0.x += a[i].x;   s0.y += a[i].y;   s0.z += a[i].z;   s0.w += a[i].w;
        s1.x += a[i+1].x; s1.y += a[i+1].y; s1.z += a[i+1].z; s1.w += a[i+1].w;
    }
    float4 s;
    s.x = s0.x + s1.x + a[6].x;
    s.y = s0.y + s1.y + a[6].y;
    s.z = s0.z + s1.z + a[6].z;
    s.w = s0.w + s1.w + a[6].w;

    __shared__ float4 sm[4][64];
    sm[y][x] = s;
    __syncthreads();
    if (y == 0) {
        float4 t = sm[0][x];
        const float4 t1 = sm[1][x], t2 = sm[2][x], t3 = sm[3][x];
        t.x += t1.x + t2.x + t3.x;
        t.y += t1.y + t2.y + t3.y;
        t.z += t1.z + t2.z + t3.z;
        t.w += t1.w + t2.w + t3.w;
        reinterpret_cast<float4*>(g_partial)[(b * CHUNKS + c) * 64 + x] = t;
    }
}

// ---------------------------------------------------------------------------
// K2: finish the mean, then 3 fused 256x256 GEMVs (+bias, ReLU between).
// One CTA per batch, 1024 threads (champion shape; only CHUNKS changed).
// ---------------------------------------------------------------------------
__global__ void k_gcn_head(const float* __restrict__ Ws, const float* __restrict__ bs) {
    const int b = blockIdx.x;
    const int t = threadIdx.x;
    const int o = t & (DD - 1);
    const int g = t >> 8;       // 0..3

    __shared__ float sv[DD];
    __shared__ float part[4][DD];

    float s = 0.f;
#pragma unroll
    for (int c = g; c < CHUNKS; c += 4)
        s += g_partial[(b * CHUNKS + c) * DD + o];
    part[g][o] = s;
    __syncthreads();
    if (g == 0)
        sv[o] = (part[0][o] + part[1][o] + part[2][o] + part[3][o]) * (1.0f / (float)NN);
    __syncthreads();

#pragma unroll
    for (int l = 0; l < LL; l++) {
        const float* __restrict__ W = Ws + l * DD * DD;
        float acc = 0.f;
        const int k0 = g * 64;
#pragma unroll 8
        for (int k = k0; k < k0 + 64; k++)
            acc = fmaf(sv[k], W[k * DD + o], acc);   // coalesced, L2-resident
        part[g][o] = acc;
        __syncthreads();
        if (g == 0) {
            float r = part[0][o] + part[1][o] + part[2][o] + part[3][o] + bs[l * DD + o];
            sv[o] = (l < LL - 1) ? fmaxf(r, 0.f) : r;
        }
        __syncthreads();
    }
    if (g == 0) g_v[b * DD + o] = sv[o];
}

// ---------------------------------------------------------------------------
// K3: out[0:BND] = nf + v[b,:] ; out[BND:2BND] = nf.
// Div-free: batch on grid.y, v[b] staged in smem. grid (50, 32), block 256.
// 5 front-batched loads + 10 __stcs stores per thread; 50*256*5 = 64000 = B4.
// ---------------------------------------------------------------------------
__global__ __launch_bounds__(256)
void k_out(const float* __restrict__ nf, float* __restrict__ out) {
    const int b = blockIdx.y;
    const int t = threadIdx.x;

    __shared__ float4 sv4[64];
    if (t < 64)
        sv4[t] = reinterpret_cast<const float4*>(g_v)[b * 64 + t];
    __syncthreads();

    const float4* __restrict__ nf4 = reinterpret_cast<const float4*>(nf) + (size_t)b * B4;
    float4* oa = reinterpret_cast<float4*>(out) + (size_t)b * B4;            // add half
    float4* oc = reinterpret_cast<float4*>(out) + TOTAL4 + (size_t)b * B4;   // copy half

    const int i0 = blockIdx.x * 256 + t;   // 0..12799
    // 5 strided slots, 12800 apart: covers [0, 64000)
    const int j0 = i0, j1 = i0 + 12800, j2 = i0 + 25600, j3 = i0 + 38400, j4 = i0 + 51200;

    const float4 a0 = nf4[j0];
    const float4 a1 = nf4[j1];
    const float4 a2 = nf4[j2];
    const float4 a3 = nf4[j3];
    const float4 a4 = nf4[j4];

#define DO_ONE(jj, aa)                                                        \
    {                                                                         \
        const float4 v = sv4[(jj) & 63];                                      \
        float4 r;                                                             \
        r.x = (aa).x + v.x; r.y = (aa).y + v.y;                               \
        r.z = (aa).z + v.z; r.w = (aa).w + v.w;                               \
        __stcs(oa + (jj), r);                                                 \
        __stcs(oc + (jj), (aa));                                              \
    }
    DO_ONE(j0, a0)
    DO_ONE(j1, a1)
    DO_ONE(j2, a2)
    DO_ONE(j3, a3)
    DO_ONE(j4, a4)
#undef DO_ONE
}

extern "C" void kernel_launch(void* const* d_in, const int* in_sizes, int n_in,
                              void* d_out, int out_size) {
    // Inputs in metadata order: x (unused), node_feature, Ws, bs
    const float* nf = (const float*)d_in[1];
    const float* Ws = (const float*)d_in[2];
    const float* bs = (const float*)d_in[3];
    float* out = (float*)d_out;

    dim3 g1(BB, CHUNKS);      // 1152 CTAs — single wave
    dim3 b1(64, 4);
    k_partial_mean<<<g1, b1>>>(nf);

    k_gcn_head<<<BB, 1024>>>(Ws, bs);

    dim3 g3(50, BB);          // 1600 CTAs
    k_out<<<g3, 256>>>(nf, out);
}

// round 15
// speedup vs baseline: 1.4363x; 1.0483x over previous
#include <cuda_runtime.h>

// B, N, D, L = 32, 1000, 256, 3
#define BB 32
#define NN 1000
#define DD 256
#define LL 3
#define CHUNKS 36
#define ROWS_PER_CHUNK 28          // 36 * 28 = 1008 >= 1000 (guarded)
#define TOTAL4 (BB * NN * DD / 4)  // 2,048,000 float4 per output half
#define B4 (NN * DD / 4)           // 64,000 float4 per batch

// Scratch (no device allocation allowed -> __device__ globals)
__device__ float g_partial[BB * CHUNKS * DD];
__device__ float g_v[BB * DD];

// ---------------------------------------------------------------------------
// K1: partial sums over the node axis — single wave (R13 shape).
// Triggers PDL immediately so K2 can pre-launch and park in its sync.
// ---------------------------------------------------------------------------
__global__ __launch_bounds__(256)
void k_partial_mean(const float* __restrict__ nf) {
    cudaTriggerProgrammaticLaunchCompletion();   // let K2 pre-launch now

    const int b = blockIdx.x;
    const int c = blockIdx.y;
    const int x = threadIdx.x;   // 0..63
    const int y = threadIdx.y;   // 0..3

    const float4* __restrict__ nf4 = reinterpret_cast<const float4*>(nf);
    const float4 z4 = make_float4(0.f, 0.f, 0.f, 0.f);
    const int row0 = c * ROWS_PER_CHUNK;
    const int base = (b * NN + row0) * 64;

    float4 a[7];
#pragma unroll
    for (int i = 0; i < 7; i++) {
        const int r = y + 4 * i;
        a[i] = (row0 + r < NN) ? nf4[base + r * 64 + x] : z4;
    }

    float4 s0 = z4, s1 = z4;
#pragma unroll
    for (int i = 0; i < 6; i += 2) {
        s0.x += a[i].x;   s0.y += a[i].y;   s0.z += a[i].z;   s0.w += a[i].w;
        s1.x += a[i+1].x; s1.y += a[i+1].y; s1.z += a[i+1].z; s1.w += a[i+1].w;
    }
    float4 s;
    s.x = s0.x + s1.x + a[6].x;
    s.y = s0.y + s1.y + a[6].y;
    s.z = s0.z + s1.z + a[6].z;
    s.w = s0.w + s1.w + a[6].w;

    __shared__ float4 sm[4][64];
    sm[y][x] = s;
    __syncthreads();
    if (y == 0) {
        float4 t = sm[0][x];
        const float4 t1 = sm[1][x], t2 = sm[2][x], t3 = sm[3][x];
        t.x += t1.x + t2.x + t3.x;
        t.y += t1.y + t2.y + t3.y;
        t.z += t1.z + t2.z + t3.z;
        t.w += t1.w + t2.w + t3.w;
        reinterpret_cast<float4*>(g_partial)[(b * CHUNKS + c) * 64 + x] = t;
    }
}

// ---------------------------------------------------------------------------
// K2: GEMV head (champion 1024-thread / K-split-4 shape).
// Syncs on K1 completion FIRST, then triggers so K3 launches and runs its
// copy-half prologue concurrently with this kernel (not with K1's read).
// ---------------------------------------------------------------------------
__global__ __launch_bounds__(1024)
void k_gcn_head(const float* __restrict__ Ws, const float* __restrict__ bs) {
    cudaGridDependencySynchronize();             // wait for K1 (partials visible)
    cudaTriggerProgrammaticLaunchCompletion();   // let K3 pre-launch now

    const int b = blockIdx.x;
    const int t = threadIdx.x;
    const int o = t & (DD - 1);
    const int g = t >> 8;       // 0..3

    __shared__ float sv[DD];
    __shared__ float part[4][DD];

    float s = 0.f;
#pragma unroll
    for (int c = g; c < CHUNKS; c += 4)
        s += g_partial[(b * CHUNKS + c) * DD + o];
    part[g][o] = s;
    __syncthreads();
    if (g == 0)
        sv[o] = (part[0][o] + part[1][o] + part[2][o] + part[3][o]) * (1.0f / (float)NN);
    __syncthreads();

#pragma unroll
    for (int l = 0; l < LL; l++) {
        const float* __restrict__ W = Ws + l * DD * DD;
        float acc = 0.f;
        const int k0 = g * 64;
#pragma unroll 8
        for (int k = k0; k < k0 + 64; k++)
            acc = fmaf(sv[k], W[k * DD + o], acc);   // coalesced, L2-resident
        part[g][o] = acc;
        __syncthreads();
        if (g == 0) {
            float r = part[0][o] + part[1][o] + part[2][o] + part[3][o] + bs[l * DD + o];
            sv[o] = (l < LL - 1) ? fmaxf(r, 0.f) : r;
        }
        __syncthreads();
    }
    if (g == 0) g_v[b * DD + o] = sv[o];
}

// ---------------------------------------------------------------------------
// K3: PDL prologue = nf loads + copy-half stores (independent of v, overlaps
// K2's GEMV); then sync on K2, stage v[b] in smem, write add half.
// Div-free R13 shape: grid (50, 32), block 256; 5 f4 per thread per half.
// ---------------------------------------------------------------------------
__global__ __launch_bounds__(256)
void k_out(const float* __restrict__ nf, float* __restrict__ out) {
    const int b = blockIdx.y;
    const int t = threadIdx.x;

    const float4* __restrict__ nf4 = reinterpret_cast<const float4*>(nf) + (size_t)b * B4;
    float4* oa = reinterpret_cast<float4*>(out) + (size_t)b * B4;            // add half
    float4* oc = reinterpret_cast<float4*>(out) + TOTAL4 + (size_t)b * B4;   // copy half

    const int i0 = blockIdx.x * 256 + t;   // 0..12799
    const int j0 = i0, j1 = i0 + 12800, j2 = i0 + 25600, j3 = i0 + 38400, j4 = i0 + 51200;

    // ---- prologue (runs concurrent with K2): load + copy half ----
    const float4 a0 = nf4[j0];
    const float4 a1 = nf4[j1];
    const float4 a2 = nf4[j2];
    const float4 a3 = nf4[j3];
    const float4 a4 = nf4[j4];

    __stcs(oc + j0, a0);
    __stcs(oc + j1, a1);
    __stcs(oc + j2, a2);
    __stcs(oc + j3, a3);
    __stcs(oc + j4, a4);

    // ---- wait for K2: v ready ----
    cudaGridDependencySynchronize();

    __shared__ float4 sv4[64];
    if (t < 64)
        sv4[t] = reinterpret_cast<const float4*>(g_v)[b * 64 + t];
    __syncthreads();

#define DO_ONE(jj, aa)                                                        \
    {                                                                         \
        const float4 v = sv4[(jj) & 63];                                      \
        float4 r;                                                             \
        r.x = (aa).x + v.x; r.y = (aa).y + v.y;                               \
        r.z = (aa).z + v.z; r.w = (aa).w + v.w;                               \
        __stcs(oa + (jj), r);                                                 \
    }
    DO_ONE(j0, a0)
    DO_ONE(j1, a1)
    DO_ONE(j2, a2)
    DO_ONE(j3, a3)
    DO_ONE(j4, a4)
#undef DO_ONE
}

extern "C" void kernel_launch(void* const* d_in, const int* in_sizes, int n_in,
                              void* d_out, int out_size) {
    // Inputs in metadata order: x (unused), node_feature, Ws, bs
    const float* nf = (const float*)d_in[1];
    const float* Ws = (const float*)d_in[2];
    const float* bs = (const float*)d_in[3];
    float* out = (float*)d_out;

    // K1: plain launch
    dim3 g1(BB, CHUNKS);
    dim3 b1(64, 4);
    k_partial_mean<<<g1, b1>>>(nf);

    // K2: PDL secondary of K1
    {
        cudaLaunchConfig_t cfg = {};
        cfg.gridDim = dim3(BB);
        cfg.blockDim = dim3(1024);
        cfg.stream = 0;
        cudaLaunchAttribute attr[1];
        attr[0].id = cudaLaunchAttributeProgrammaticStreamSerialization;
        attr[0].val.programmaticStreamSerializationAllowed = 1;
        cfg.attrs = attr;
        cfg.numAttrs = 1;
        cudaLaunchKernelEx(&cfg, k_gcn_head, Ws, bs);
    }

    // K3: PDL secondary of K2
    {
        cudaLaunchConfig_t cfg = {};
        cfg.gridDim = dim3(50, BB);
        cfg.blockDim = dim3(256);
        cfg.stream = 0;
        cudaLaunchAttribute attr[1];
        attr[0].id = cudaLaunchAttributeProgrammaticStreamSerialization;
        attr[0].val.programmaticStreamSerializationAllowed = 1;
        cfg.attrs = attr;
        cfg.numAttrs = 1;
        cudaLaunchKernelEx(&cfg, k_out, nf, out);
    }
}